// round 1
// baseline (speedup 1.0000x reference)
#include <cuda_runtime.h>
#include <math.h>

// Router: logits = x @ Wg ; probs = softmax(logits) ; top-2 ; combine renorm.
// x: [T=65536, D=1024] f32, Wg: [D=1024, E=64] f32, top_k = 2 (constant).
// Output layout (concatenated, all f32):
//   [0,            T*2)  combine
//   [T*2,          T*4)  topk_idx (cast to float)
//   [T*4,          T*68) probs
#define T_TOK 65536
#define D_DIM 1024
#define E_EXP 64
#define BM 64
#define BK 16
#define NTHREADS 256

__global__ __launch_bounds__(NTHREADS)
void router_kernel(const float* __restrict__ x,
                   const float* __restrict__ Wg,
                   float* __restrict__ out) {
    __shared__ float As[BK][BM];          // x tile, transposed: As[k][m]
    __shared__ float Bs[BK][E_EXP];       // Wg tile: Bs[k][e]
    __shared__ float Ls[BM][E_EXP + 1];   // logits -> exp values (padded stride)
    __shared__ float inv_sum[BM];

    const int tid = threadIdx.x;
    const int m0  = blockIdx.x * BM;

    // ---- global load mapping ----
    const int am  = tid >> 2;   // 0..63 : token row within tile
    const int ac4 = tid & 3;    // 0..3  : which float4 along k
    const int bk  = tid >> 4;   // 0..15 : k row of Wg tile
    const int be4 = tid & 15;   // 0..15 : float4 along experts

    const float4* xg = (const float4*)(x + (size_t)(m0 + am) * D_DIM) + ac4;
    const float4* wg = (const float4*)Wg + (size_t)bk * (E_EXP / 4) + be4;

    float4 a_next = xg[0];
    float4 b_next = wg[0];

    // ---- compute mapping: 4x4 micro-tile ----
    const int ty = tid >> 4;  // 0..15 : token group (4 tokens)
    const int tx = tid & 15;  // 0..15 : expert group (4 experts)

    float acc[4][4];
    #pragma unroll
    for (int i = 0; i < 4; i++)
        #pragma unroll
        for (int j = 0; j < 4; j++) acc[i][j] = 0.0f;

    const int KT = D_DIM / BK;  // 64
    for (int kt = 0; kt < KT; ++kt) {
        // stage prefetched regs into smem
        As[ac4 * 4 + 0][am] = a_next.x;
        As[ac4 * 4 + 1][am] = a_next.y;
        As[ac4 * 4 + 2][am] = a_next.z;
        As[ac4 * 4 + 3][am] = a_next.w;
        *((float4*)&Bs[bk][be4 * 4]) = b_next;
        __syncthreads();

        if (kt + 1 < KT) {
            a_next = xg[(kt + 1) * (BK / 4)];                 // +4 float4 per tile
            b_next = wg[(size_t)(kt + 1) * (BK * E_EXP / 4)]; // +256 float4 per tile
        }

        #pragma unroll
        for (int k = 0; k < BK; ++k) {
            float4 av = *((const float4*)&As[k][ty * 4]);
            float4 bv = *((const float4*)&Bs[k][tx * 4]);
            acc[0][0] += av.x * bv.x; acc[0][1] += av.x * bv.y;
            acc[0][2] += av.x * bv.z; acc[0][3] += av.x * bv.w;
            acc[1][0] += av.y * bv.x; acc[1][1] += av.y * bv.y;
            acc[1][2] += av.y * bv.z; acc[1][3] += av.y * bv.w;
            acc[2][0] += av.z * bv.x; acc[2][1] += av.z * bv.y;
            acc[2][2] += av.z * bv.z; acc[2][3] += av.z * bv.w;
            acc[3][0] += av.w * bv.x; acc[3][1] += av.w * bv.y;
            acc[3][2] += av.w * bv.z; acc[3][3] += av.w * bv.w;
        }
        __syncthreads();
    }

    // ---- stash logits tile into smem ----
    #pragma unroll
    for (int i = 0; i < 4; i++)
        #pragma unroll
        for (int j = 0; j < 4; j++)
            Ls[ty * 4 + i][tx * 4 + j] = acc[i][j];
    __syncthreads();

    // ---- per-token softmax + top-2 (one thread per token) ----
    if (tid < BM) {
        const int t = tid;
        float mx = -1e30f;
        #pragma unroll
        for (int e = 0; e < E_EXP; e++) mx = fmaxf(mx, Ls[t][e]);

        float sum = 0.0f;
        float v1 = -1.0f, v2 = -1.0f;
        int   i1 = 0,     i2 = 0;
        #pragma unroll 8
        for (int e = 0; e < E_EXP; e++) {
            float p = expf(Ls[t][e] - mx);
            Ls[t][e] = p;           // overwrite with exp value for phase 2
            sum += p;
            if (p > v1)      { v2 = v1; i2 = i1; v1 = p; i1 = e; }
            else if (p > v2) { v2 = p;  i2 = e; }
        }
        inv_sum[t] = 1.0f / sum;

        const float cd = 1.0f / (v1 + v2);
        const int gt = m0 + t;
        *(float2*)(out + (size_t)gt * 2) = make_float2(v1 * cd, v2 * cd);
        *(float2*)(out + (size_t)T_TOK * 2 + (size_t)gt * 2) =
            make_float2((float)i1, (float)i2);
    }
    __syncthreads();

    // ---- coalesced probs write: 64x64 tile, float4 per thread x4 ----
    float* probs = out + (size_t)T_TOK * 4;
    #pragma unroll
    for (int it = 0; it < 4; ++it) {
        int lin = tid + it * NTHREADS;   // 0..1023
        int t = lin >> 4;                // token in tile
        int c = lin & 15;                // float4 column
        float s = inv_sum[t];
        float4 v;
        v.x = Ls[t][c * 4 + 0] * s;
        v.y = Ls[t][c * 4 + 1] * s;
        v.z = Ls[t][c * 4 + 2] * s;
        v.w = Ls[t][c * 4 + 3] * s;
        *(float4*)(probs + (size_t)(m0 + t) * E_EXP + c * 4) = v;
    }
}

extern "C" void kernel_launch(void* const* d_in, const int* in_sizes, int n_in,
                              void* d_out, int out_size) {
    const float* x  = (const float*)d_in[0];
    const float* Wg = (const float*)d_in[1];
    // d_in[2] = top_k (constant 2, baked in)
    float* out = (float*)d_out;
    (void)in_sizes; (void)n_in; (void)out_size;

    dim3 grid(T_TOK / BM);   // 1024 blocks
    dim3 block(NTHREADS);
    router_kernel<<<grid, block>>>(x, Wg, out);
}

// round 6
// speedup vs baseline: 1.0739x; 1.0739x over previous
#include <cuda_runtime.h>
#include <cuda_fp16.h>
#include <cstdint>
#include <math.h>

// Router: logits = x @ Wg ; softmax ; top-2 ; renorm combine.
// x: [65536,1024] f32, Wg: [1024,64] f32.
// Out f32: [0,2T) combine | [2T,4T) idx | [4T,68T) probs.
//
// fp16 hi/lo split GEMM on mma.sync (3 products: hh + hl + lh), fp32 accum
// => logits accurate to ~5e-7 (below fp32 summation-order noise).
// Tiny fp32 fix-up pass for tokens with top-2/3 gap < 1e-4 (a handful).

#define T_TOK 65536
#define D_DIM 1024
#define E_EXP 64
#define BM 128
#define KC 32
#define NKC (D_DIM / KC)   // 32
#define NTH 256
#define ASTRIDE 80         // bytes per smem row: 32 fp16 (64B) + 16B pad
#define TH_AMB 1.0e-4f
#define NEG_INF (-3.0e38f)

__device__ __half g_wth[E_EXP * D_DIM];  // Wg^T hi: [n][k]
__device__ __half g_wtl[E_EXP * D_DIM];  // Wg^T lo: [n][k]
__device__ int g_cnt;
__device__ int g_list[T_TOK];

// ---------- helpers ----------
__device__ __forceinline__ void split2(float a, float b, uint32_t& hi, uint32_t& lo) {
    __half ha = __float2half_rn(a), hb = __float2half_rn(b);
    __half la = __float2half_rn(a - __half2float(ha));
    __half lb = __float2half_rn(b - __half2float(hb));
    __half2 H = __halves2half2(ha, hb), L = __halves2half2(la, lb);
    hi = *(uint32_t*)&H; lo = *(uint32_t*)&L;
}

__device__ __forceinline__ void ldm4(uint32_t& r0, uint32_t& r1, uint32_t& r2,
                                     uint32_t& r3, uint32_t addr) {
    asm volatile("ldmatrix.sync.aligned.m8n8.x4.shared.b16 {%0,%1,%2,%3}, [%4];"
                 : "=r"(r0), "=r"(r1), "=r"(r2), "=r"(r3) : "r"(addr));
}

__device__ __forceinline__ void mma_f16(float* c, uint32_t a0, uint32_t a1,
                                        uint32_t a2, uint32_t a3,
                                        uint32_t b0, uint32_t b1) {
    asm volatile(
        "mma.sync.aligned.m16n8k16.row.col.f32.f16.f16.f32 "
        "{%0,%1,%2,%3}, {%4,%5,%6,%7}, {%8,%9}, {%0,%1,%2,%3};"
        : "+f"(c[0]), "+f"(c[1]), "+f"(c[2]), "+f"(c[3])
        : "r"(a0), "r"(a1), "r"(a2), "r"(a3), "r"(b0), "r"(b1));
}

// insert (v,i) into descending top-3, lower-index tie-break (jax top_k order)
__device__ __forceinline__ void ins3(float v, int i,
                                     float& v1, int& i1, float& v2, int& i2,
                                     float& v3, int& i3) {
    if (v > v1 || (v == v1 && i < i1)) {
        v3 = v2; i3 = i2; v2 = v1; i2 = i1; v1 = v; i1 = i;
    } else if (v > v2 || (v == v2 && i < i2)) {
        v3 = v2; i3 = i2; v2 = v; i2 = i;
    } else if (v > v3 || (v == v3 && i < i3)) {
        v3 = v; i3 = i;
    }
}

// ---------- prep: Wg -> fp16 hi/lo transpose; zero counter ----------
__global__ void prep(const float* __restrict__ Wg) {
    int i = blockIdx.x * blockDim.x + threadIdx.x;  // 0..65535
    int k = i >> 6, n = i & 63;
    float w = Wg[i];
    __half h = __float2half_rn(w);
    __half l = __float2half_rn(w - __half2float(h));
    g_wth[n * D_DIM + k] = h;
    g_wtl[n * D_DIM + k] = l;
    if (i == 0) g_cnt = 0;
}

// ---------- pass 1 ----------
__global__ __launch_bounds__(NTH, 2)
void router_main(const float* __restrict__ x, float* __restrict__ out) {
    __shared__ __align__(16) unsigned char sAh[BM * ASTRIDE];     // 10240 B
    __shared__ __align__(16) unsigned char sAl[BM * ASTRIDE];     // 10240 B
    __shared__ __align__(16) unsigned char sBh[E_EXP * ASTRIDE];  //  5120 B
    __shared__ __align__(16) unsigned char sBl[E_EXP * ASTRIDE];  //  5120 B

    const int tid = threadIdx.x;
    const int w   = tid >> 5;
    const int lid = tid & 31;
    const int m0  = blockIdx.x * BM;

    const uint32_t sAhu = (uint32_t)__cvta_generic_to_shared(sAh);
    const uint32_t sAlu = (uint32_t)__cvta_generic_to_shared(sAl);
    const uint32_t sBhu = (uint32_t)__cvta_generic_to_shared(sBh);
    const uint32_t sBlu = (uint32_t)__cvta_generic_to_shared(sBl);

    float acc[8][4];
    #pragma unroll
    for (int t = 0; t < 8; ++t)
        #pragma unroll
        for (int c = 0; c < 4; ++c) acc[t][c] = 0.0f;

    const float* xbase = x + (size_t)m0 * D_DIM;

    // prefetch chunk 0
    float4 pa[4]; float4 pbh, pbl;
    #pragma unroll
    for (int i = 0; i < 4; ++i) {
        int lin = i * NTH + tid;
        pa[i] = *(const float4*)(xbase + (size_t)(lin >> 3) * D_DIM + (lin & 7) * 4);
    }
    pbh = ((const float4*)(g_wth + (size_t)(tid >> 2) * D_DIM))[tid & 3];
    pbl = ((const float4*)(g_wtl + (size_t)(tid >> 2) * D_DIM))[tid & 3];

    for (int kt = 0; kt < NKC; ++kt) {
        // stage prefetched tiles into smem (split A on the fly)
        #pragma unroll
        for (int i = 0; i < 4; ++i) {
            int lin = i * NTH + tid;
            uint32_t h0, l0, h1, l1;
            split2(pa[i].x, pa[i].y, h0, l0);
            split2(pa[i].z, pa[i].w, h1, l1);
            int off = (lin >> 3) * ASTRIDE + (lin & 7) * 8;
            *(uint2*)(sAh + off) = make_uint2(h0, h1);
            *(uint2*)(sAl + off) = make_uint2(l0, l1);
        }
        {
            int off = (tid >> 2) * ASTRIDE + (tid & 3) * 16;
            *(float4*)(sBh + off) = pbh;
            *(float4*)(sBl + off) = pbl;
        }
        __syncthreads();

        if (kt + 1 < NKC) {
            const int k0 = (kt + 1) * KC;
            #pragma unroll
            for (int i = 0; i < 4; ++i) {
                int lin = i * NTH + tid;
                pa[i] = *(const float4*)(xbase + (size_t)(lin >> 3) * D_DIM + k0 + (lin & 7) * 4);
            }
            pbh = ((const float4*)(g_wth + (size_t)(tid >> 2) * D_DIM + k0))[tid & 3];
            pbl = ((const float4*)(g_wtl + (size_t)(tid >> 2) * D_DIM + k0))[tid & 3];
        }

        // compute: 2 k16-steps, 3 split-products each
        #pragma unroll
        for (int ks = 0; ks < 2; ++ks) {
            const int m = lid >> 3, r = lid & 7;
            const uint32_t aoff = (uint32_t)((w * 16 + (m & 1) * 8 + r) * ASTRIDE
                                             + (ks * 16 + (m >> 1) * 8) * 2);
            uint32_t ah0, ah1, ah2, ah3, al0, al1, al2, al3;
            ldm4(ah0, ah1, ah2, ah3, sAhu + aoff);
            ldm4(al0, al1, al2, al3, sAlu + aoff);

            uint32_t bh[16], bl[16];
            #pragma unroll
            for (int j = 0; j < 4; ++j) {
                const uint32_t boff = (uint32_t)((j * 16 + (m >> 1) * 8 + r) * ASTRIDE
                                                 + (ks * 16 + (m & 1) * 8) * 2);
                ldm4(bh[4 * j], bh[4 * j + 1], bh[4 * j + 2], bh[4 * j + 3], sBhu + boff);
                ldm4(bl[4 * j], bl[4 * j + 1], bl[4 * j + 2], bl[4 * j + 3], sBlu + boff);
            }
            #pragma unroll
            for (int t = 0; t < 8; ++t) {
                mma_f16(acc[t], ah0, ah1, ah2, ah3, bh[2 * t], bh[2 * t + 1]);
                mma_f16(acc[t], ah0, ah1, ah2, ah3, bl[2 * t], bl[2 * t + 1]);
                mma_f16(acc[t], al0, al1, al2, al3, bh[2 * t], bh[2 * t + 1]);
            }
        }
        __syncthreads();
    }

    // ---------- fused epilogue ----------
    const int q = lid >> 2;   // row within warp tile half
    const int c = lid & 3;    // column quad lane

    #pragma unroll
    for (int rr = 0; rr < 2; ++rr) {
        float v1 = NEG_INF, v2 = NEG_INF, v3 = NEG_INF;
        int   i1 = 0, i2 = 0, i3 = 0;
        #pragma unroll
        for (int t = 0; t < 8; ++t) {
            ins3(acc[t][rr * 2 + 0], t * 8 + c * 2 + 0, v1, i1, v2, i2, v3, i3);
            ins3(acc[t][rr * 2 + 1], t * 8 + c * 2 + 1, v1, i1, v2, i2, v3, i3);
        }
        #pragma unroll
        for (int d = 1; d <= 2; d <<= 1) {
            float ov1 = __shfl_xor_sync(0xffffffffu, v1, d);
            float ov2 = __shfl_xor_sync(0xffffffffu, v2, d);
            float ov3 = __shfl_xor_sync(0xffffffffu, v3, d);
            int   oi1 = __shfl_xor_sync(0xffffffffu, i1, d);
            int   oi2 = __shfl_xor_sync(0xffffffffu, i2, d);
            int   oi3 = __shfl_xor_sync(0xffffffffu, i3, d);
            ins3(ov1, oi1, v1, i1, v2, i2, v3, i3);
            ins3(ov2, oi2, v1, i1, v2, i2, v3, i3);
            ins3(ov3, oi3, v1, i1, v2, i2, v3, i3);
        }
        float s = 0.0f;
        #pragma unroll
        for (int t = 0; t < 8; ++t) {
            float e0 = expf(acc[t][rr * 2 + 0] - v1);
            float e1 = expf(acc[t][rr * 2 + 1] - v1);
            acc[t][rr * 2 + 0] = e0;
            acc[t][rr * 2 + 1] = e1;
            s += e0 + e1;
        }
        s += __shfl_xor_sync(0xffffffffu, s, 1);
        s += __shfl_xor_sync(0xffffffffu, s, 2);
        const float inv = 1.0f / s;

        const int gt = m0 + w * 16 + q + rr * 8;
        float* pr = out + (size_t)T_TOK * 4 + (size_t)gt * E_EXP;
        #pragma unroll
        for (int t = 0; t < 8; ++t) {
            *(float2*)(pr + t * 8 + c * 2) =
                make_float2(acc[t][rr * 2] * inv, acc[t][rr * 2 + 1] * inv);
        }
        if (c == 0) {
            float e2 = expf(v2 - v1);
            float cd = 1.0f / (1.0f + e2);
            *(float2*)(out + (size_t)gt * 2) = make_float2(cd, e2 * cd);
            *(float2*)(out + (size_t)T_TOK * 2 + (size_t)gt * 2) =
                make_float2((float)i1, (float)i2);
            if ((v1 - v2 < TH_AMB) || (v2 - v3 < TH_AMB)) {
                int p = atomicAdd(&g_cnt, 1);
                g_list[p] = gt;
            }
        }
    }
}

// ---------- pass 2: exact fp32 fix-up for ambiguous tokens ----------
__global__ __launch_bounds__(128)
void router_fixup(const float* __restrict__ x, const float* __restrict__ Wg,
                  float* __restrict__ out) {
    const int lid = threadIdx.x & 31;
    const int gw  = (blockIdx.x * blockDim.x + threadIdx.x) >> 5;
    const int nw  = (gridDim.x * blockDim.x) >> 5;
    const int cnt = g_cnt;
    const float2* W2 = (const float2*)Wg;  // [1024][32] expert pairs

    for (int idx = gw; idx < cnt; idx += nw) {
        const int t = g_list[idx];
        const float* xr = x + (size_t)t * D_DIM;
        float ax = 0.0f, ay = 0.0f;  // experts 2*lid, 2*lid+1
        for (int k0 = 0; k0 < D_DIM; k0 += 32) {
            float xv = xr[k0 + lid];
            #pragma unroll
            for (int kk = 0; kk < 32; ++kk) {
                float v = __shfl_sync(0xffffffffu, xv, kk);
                float2 wv = W2[(size_t)(k0 + kk) * 32 + lid];
                ax = fmaf(v, wv.x, ax);
                ay = fmaf(v, wv.y, ay);
            }
        }
        float v1 = NEG_INF, v2 = NEG_INF, v3 = NEG_INF;
        int   i1 = 0, i2 = 0, i3 = 0;
        ins3(ax, 2 * lid + 0, v1, i1, v2, i2, v3, i3);
        ins3(ay, 2 * lid + 1, v1, i1, v2, i2, v3, i3);
        #pragma unroll
        for (int d = 1; d < 32; d <<= 1) {
            float ov1 = __shfl_xor_sync(0xffffffffu, v1, d);
            float ov2 = __shfl_xor_sync(0xffffffffu, v2, d);
            float ov3 = __shfl_xor_sync(0xffffffffu, v3, d);
            int   oi1 = __shfl_xor_sync(0xffffffffu, i1, d);
            int   oi2 = __shfl_xor_sync(0xffffffffu, i2, d);
            int   oi3 = __shfl_xor_sync(0xffffffffu, i3, d);
            ins3(ov1, oi1, v1, i1, v2, i2, v3, i3);
            ins3(ov2, oi2, v1, i1, v2, i2, v3, i3);
            ins3(ov3, oi3, v1, i1, v2, i2, v3, i3);
        }
        float ex = expf(ax - v1), ey = expf(ay - v1);
        float s = ex + ey;
        #pragma unroll
        for (int d = 1; d < 32; d <<= 1) s += __shfl_xor_sync(0xffffffffu, s, d);
        const float inv = 1.0f / s;

        *(float2*)(out + (size_t)T_TOK * 4 + (size_t)t * E_EXP + 2 * lid) =
            make_float2(ex * inv, ey * inv);
        if (lid == 0) {
            float e2 = expf(v2 - v1);
            float cd = 1.0f / (1.0f + e2);
            *(float2*)(out + (size_t)t * 2) = make_float2(cd, e2 * cd);
            *(float2*)(out + (size_t)T_TOK * 2 + (size_t)t * 2) =
                make_float2((float)i1, (float)i2);
        }
    }
}

extern "C" void kernel_launch(void* const* d_in, const int* in_sizes, int n_in,
                              void* d_out, int out_size) {
    const float* x  = (const float*)d_in[0];
    const float* Wg = (const float*)d_in[1];
    float* out = (float*)d_out;
    (void)in_sizes; (void)n_in; (void)out_size;

    prep<<<256, 256>>>(Wg);
    router_main<<<T_TOK / BM, NTH>>>(x, out);
    router_fixup<<<128, 128>>>(x, Wg, out);
}